// round 1
// baseline (speedup 1.0000x reference)
#include <cuda_runtime.h>
#include <math.h>

#define NN   4096
#define RR   4
#define FINN 128
#define HH   64
#define CC   16
#define LLAY 2
#define TT   512
#define ELL_S 128   // max nnz per row (mean ~21.5, sigma ~4.5 -> 24 sigma margin)

// cos(2*pi*k*r/4): the real-part DFT matrix for length-4 FFT. Rows 1 and 3 identical.
__device__ __constant__ float Mc[4][4] = {
  { 1.f,  1.f,  1.f,  1.f},
  { 1.f,  0.f, -1.f,  0.f},
  { 1.f, -1.f,  1.f, -1.f},
  { 1.f,  0.f, -1.f,  0.f}
};

// ---- static scratch (no runtime allocation allowed) ----
__device__ float g_d   [RR*NN];              // D^-1/2 per (relation,row)
__device__ int   g_cnt [RR*NN];              // nnz per row (incl. forced diagonal)
__device__ int   g_cols[RR*NN*ELL_S];        // ELL column indices (8 MB)
__device__ float g_Y   [RR*NN*HH];           // dense feature @ weight results
__device__ float g_h   [RR*NN*HH];           // GCN hidden
__device__ float g_tX  [NN*HH*RR];           // [i][h][r] layout (== flatten order)
__device__ float g_Xhat[3*NN*HH];            // frequency-domain features, k=0..2
__device__ float g_Chat[3*NN*HH];            // Chat, then in-place Ohat
__device__ float g_Dhat[3*NN*HH];
__device__ float g_What[3*HH*HH];
__device__ float g_losses[TT];
__device__ float g_yscratch[TT*CC];

// ------------------------------------------------------------------
// K1: one pass over dense A: build ELL pattern + degrees + d = deg^-1/2.
// A entries are exactly 0.0/1.0; diagonal is forced present (set to 1.0).
// One warp per (r,i) row; ballot+popc gives ordered compaction.
// ------------------------------------------------------------------
__global__ void k_build(const float* __restrict__ A) {
    int warp = (blockIdx.x * blockDim.x + threadIdx.x) >> 5;
    int lane = threadIdx.x & 31;
    if (warp >= RR * NN) return;
    int r = warp / NN, i = warp % NN;
    const float* row = A + ((size_t)r * NN + i) * NN;
    int* crow = g_cols + (size_t)warp * ELL_S;
    int cnt = 0;
    for (int j0 = 0; j0 < NN; j0 += 32) {
        int j = j0 + lane;
        float v = row[j];
        bool nz = (v != 0.0f) || (j == i);   // diagonal forced to 1
        unsigned m = __ballot_sync(0xffffffffu, nz);
        if (nz) {
            int pos = cnt + __popc(m & ((1u << lane) - 1u));
            if (pos < ELL_S) crow[pos] = j;
        }
        cnt += __popc(m);
    }
    if (cnt > ELL_S) cnt = ELL_S;            // statistically unreachable
    if (lane == 0) {
        g_cnt[warp] = cnt;
        // rowsum = cnt exactly (all stored values are 1.0); cnt>=1 so clip is a no-op
        g_d[warp] = rsqrtf((float)cnt);
    }
}

// K2: Y[r,j,:] = X[j,:] @ W1[r]   ([4096,128]@[128,64] per relation)
__global__ void k_xw1(const float* __restrict__ X, const float* __restrict__ W1) {
    int j = blockIdx.x, r = blockIdx.y, h = threadIdx.x;
    __shared__ float sx[FINN];
    for (int f = h; f < FINN; f += HH) sx[f] = X[(size_t)j * FINN + f];
    __syncthreads();
    const float* w = W1 + (size_t)r * FINN * HH;
    float acc = 0.f;
    #pragma unroll 8
    for (int f = 0; f < FINN; f++) acc += sx[f] * w[f * HH + h];
    g_Y[((size_t)r * NN + j) * HH + h] = acc;
}

// K4a: Y[r,j,:] = h[r,j,:] @ W2[r]   ([4096,64]@[64,64] per relation)
__global__ void k_hw2(const float* __restrict__ W2) {
    int j = blockIdx.x, r = blockIdx.y, h = threadIdx.x;
    __shared__ float sx[HH];
    sx[h] = g_h[((size_t)r * NN + j) * HH + h];
    __syncthreads();
    const float* w = W2 + (size_t)r * HH * HH;
    float acc = 0.f;
    #pragma unroll 8
    for (int f = 0; f < HH; f++) acc += sx[f] * w[f * HH + h];
    g_Y[((size_t)r * NN + j) * HH + h] = acc;
}

// K3/K4b: h[r,i,:] = relu(d_ri * sum_{j in nnz} d_rj * Y[r,j,:] + bias[r,:])
// to_tx=1 writes into the [i][h][r] layout for the MRGCO stage.
__global__ void k_spmm_gcn(const float* __restrict__ bias, int to_tx) {
    int i = blockIdx.x, r = blockIdx.y, h = threadIdx.x;
    int row = r * NN + i;
    int cnt = g_cnt[row];
    __shared__ int   sc[ELL_S];
    __shared__ float sw[ELL_S];
    const int* crow = g_cols + (size_t)row * ELL_S;
    for (int s = h; s < cnt; s += HH) { int j = crow[s]; sc[s] = j; sw[s] = g_d[r * NN + j]; }
    __syncthreads();
    float acc = 0.f;
    for (int s = 0; s < cnt; s++)
        acc += sw[s] * g_Y[((size_t)r * NN + sc[s]) * HH + h];
    float v = g_d[row] * acc + bias[r * HH + h];
    v = v > 0.f ? v : 0.f;
    if (to_tx) g_tX[((size_t)i * HH + h) * RR + r] = v;
    else       g_h[(size_t)row * HH + h] = v;
}

// MRGCO: Xhat_k[j,h] = sum_r M[k,r] * tX[j,h,r]  (k=0..2; k=3 duplicates k=1)
__global__ void k_xhat() {
    int idx = blockIdx.x * blockDim.x + threadIdx.x;
    if (idx >= NN * HH) return;
    const float* p = g_tX + (size_t)idx * RR;
    float x0 = p[0], x1 = p[1], x2 = p[2], x3 = p[3];
    g_Xhat[idx]             = x0 + x1 + x2 + x3;
    g_Xhat[NN*HH + idx]     = x0 - x2;
    g_Xhat[2*NN*HH + idx]   = x0 - x1 + x2 - x3;
}

// Chat_k[i,h] = sum_r M[k,r] * d_ri * sum_{j in nnz_r(i)} d_rj * Xhat_k[j,h]
// One sparse pass computes all 3 frequencies for all 4 relations.
__global__ void k_spmm3() {
    int i = blockIdx.x, h = threadIdx.x;
    __shared__ int   sc[ELL_S];
    __shared__ float sw[ELL_S];
    float c0 = 0.f, c1 = 0.f, c2 = 0.f;
    for (int r = 0; r < RR; r++) {
        int row = r * NN + i;
        int cnt = g_cnt[row];
        __syncthreads();
        const int* crow = g_cols + (size_t)row * ELL_S;
        for (int s = h; s < cnt; s += HH) { int j = crow[s]; sc[s] = j; sw[s] = g_d[r * NN + j]; }
        __syncthreads();
        float s0 = 0.f, s1 = 0.f, s2 = 0.f;
        for (int s = 0; s < cnt; s++) {
            float w = sw[s]; int j = sc[s];
            s0 += w * g_Xhat[(size_t)j * HH + h];
            s1 += w * g_Xhat[NN*HH + (size_t)j * HH + h];
            s2 += w * g_Xhat[2*NN*HH + (size_t)j * HH + h];
        }
        float di = g_d[row];
        c0 += Mc[0][r] * di * s0;
        c1 += Mc[1][r] * di * s1;
        c2 += Mc[2][r] * di * s2;
    }
    g_Chat[(size_t)i * HH + h]           = c0;
    g_Chat[NN*HH + (size_t)i * HH + h]   = c1;
    g_Chat[2*NN*HH + (size_t)i * HH + h] = c2;
}

// O1_r = 0.25*(M[r,0]C0 + 2*M[r,1]C1 + M[r,2]C2)  (ifft.real; k=3 term folded into k=1)
// Ohat_k = sum_r M[k,r] O1_r  (fft.real of next tensor_product). In-place on g_Chat.
__global__ void k_ohat() {
    int idx = blockIdx.x * blockDim.x + threadIdx.x;
    if (idx >= NN * HH) return;
    float C0 = g_Chat[idx], C1 = g_Chat[NN*HH + idx], C2 = g_Chat[2*NN*HH + idx];
    float O1[4];
    #pragma unroll
    for (int r = 0; r < 4; r++)
        O1[r] = 0.25f * (Mc[r][0] * C0 + 2.f * Mc[r][1] * C1 + Mc[r][2] * C2);
    #pragma unroll
    for (int k = 0; k < 3; k++) {
        float o = 0.f;
        #pragma unroll
        for (int r = 0; r < 4; r++) o += Mc[k][r] * O1[r];
        g_Chat[k * NN*HH + idx] = o;
    }
}

// What_k[j,l] = sum_r M[k,r] * W[j,l,r]
__global__ void k_what(const float* __restrict__ W) {
    int idx = blockIdx.x * blockDim.x + threadIdx.x;
    if (idx >= HH * HH) return;
    const float* p = W + (size_t)idx * RR;
    float w0 = p[0], w1 = p[1], w2 = p[2], w3 = p[3];
    g_What[idx]             = w0 + w1 + w2 + w3;
    g_What[HH*HH + idx]     = w0 - w2;
    g_What[2*HH*HH + idx]   = w0 - w1 + w2 - w3;
}

// Dhat_k = Ohat_k @ What_k   ([4096,64]@[64,64], k=0..2). Ohat lives in g_Chat.
__global__ void k_dhat() {
    int k = blockIdx.y;
    int l = threadIdx.x, ii = threadIdx.y;
    int i = blockIdx.x * 8 + ii;
    __shared__ float sW[HH * HH];
    __shared__ float sO[8][HH];
    int tid = ii * HH + l;
    for (int q = tid; q < HH * HH; q += 512) sW[q] = g_What[k * HH*HH + q];
    sO[ii][l] = g_Chat[k * NN*HH + (size_t)i * HH + l];
    __syncthreads();
    float acc = 0.f;
    #pragma unroll 8
    for (int j = 0; j < HH; j++) acc += sO[ii][j] * sW[j * HH + l];
    g_Dhat[k * NN*HH + (size_t)i * HH + l] = acc;
}

// O2_r = 0.25*(M[r,0]D0 + 2*M[r,1]D1 + M[r,2]D2); tX = relu(O2) back in [i][h][r]
__global__ void k_o2relu() {
    int idx = blockIdx.x * blockDim.x + threadIdx.x;
    if (idx >= NN * HH) return;
    float D0 = g_Dhat[idx], D1 = g_Dhat[NN*HH + idx], D2 = g_Dhat[2*NN*HH + idx];
    #pragma unroll
    for (int r = 0; r < 4; r++) {
        float v = 0.25f * (Mc[r][0] * D0 + 2.f * Mc[r][1] * D1 + Mc[r][2] * D2);
        g_tX[(size_t)idx * RR + r] = v > 0.f ? v : 0.f;
    }
}

// Head: only the T=512 gathered rows. flat row (h,r) == g_tX row (contiguous 256 floats).
__global__ void k_head(const int* __restrict__ target_x, const int* __restrict__ target,
                       const float* __restrict__ l1w, const float* __restrict__ l1b,
                       const float* __restrict__ l2w, const float* __restrict__ l2b,
                       float* __restrict__ y_out) {
    int t = blockIdx.x, tid = threadIdx.x;  // 64 threads
    __shared__ float sf[HH * RR];
    __shared__ float sz[HH];
    __shared__ float sy[CC];
    int n = target_x[t];
    for (int q = tid; q < HH * RR; q += HH) sf[q] = g_tX[(size_t)n * HH * RR + q];
    __syncthreads();
    float acc = l1b[tid];
    #pragma unroll 8
    for (int q = 0; q < HH * RR; q++) acc += sf[q] * l1w[q * HH + tid];
    sz[tid] = acc > 0.f ? acc : 0.f;
    __syncthreads();
    if (tid < CC) {
        float yv = l2b[tid];
        #pragma unroll 8
        for (int hh = 0; hh < HH; hh++) yv += sz[hh] * l2w[hh * CC + tid];
        sy[tid] = yv;
        y_out[t * CC + tid] = yv;
    }
    __syncthreads();
    if (tid == 0) {
        float mx = sy[0];
        for (int c = 1; c < CC; c++) mx = fmaxf(mx, sy[c]);
        float se = 0.f;
        for (int c = 0; c < CC; c++) se += expf(sy[c] - mx);
        float lse = mx + logf(se);
        g_losses[t] = lse - sy[target[t]];   // -logp[target]
    }
}

// Deterministic fixed-order tree reduction of the 512 per-sample losses.
__global__ void k_loss_reduce(float* __restrict__ loss_ptr) {
    __shared__ float s[256];
    int tid = threadIdx.x;
    s[tid] = g_losses[tid] + g_losses[tid + 256];
    __syncthreads();
    for (int o = 128; o > 0; o >>= 1) {
        if (tid < o) s[tid] += s[tid + o];
        __syncthreads();
    }
    if (tid == 0) *loss_ptr = s[0] / (float)TT;
}

extern "C" void kernel_launch(void* const* d_in, const int* in_sizes, int n_in,
                              void* d_out, int out_size) {
    const float* A        = (const float*)d_in[0];
    const float* X        = (const float*)d_in[1];
    const int*   target_x = (const int*)  d_in[2];
    const int*   target   = (const int*)  d_in[3];
    const float* gw1      = (const float*)d_in[4];
    const float* gb1      = (const float*)d_in[5];
    const float* gw2      = (const float*)d_in[6];
    const float* gb2      = (const float*)d_in[7];
    const float* mw       = (const float*)d_in[8];
    const float* l1w      = (const float*)d_in[9];
    const float* l1b      = (const float*)d_in[10];
    const float* l2w      = (const float*)d_in[11];
    const float* l2b      = (const float*)d_in[12];

    float* outf = (float*)d_out;
    float* loss_ptr = nullptr;
    float* y_ptr    = nullptr;
    if (out_size >= TT * CC + 1)      { loss_ptr = outf; y_ptr = outf + 1; }  // (loss, y) flattened
    else if (out_size >= TT * CC)     { y_ptr = outf; }
    else                              { loss_ptr = outf; }
    if (!y_ptr) { cudaMemcpyToSymbol(g_yscratch, &outf, 0); }  // never taken; keep symbol live
    float* y_dst = y_ptr ? y_ptr : nullptr;
    if (!y_dst) {
        // fall back to device scratch (loss-only output case)
        void* p = nullptr;
        cudaGetSymbolAddress(&p, g_yscratch);
        y_dst = (float*)p;
    }

    // 1) single dense pass over A -> sparsity pattern + degrees
    k_build<<<(RR * NN * 32 + 255) / 256, 256>>>(A);

    // 2) per-relation GCN x2 (sparse)
    dim3 gNR(NN, RR);
    k_xw1<<<gNR, HH>>>(X, gw1);
    k_spmm_gcn<<<gNR, HH>>>(gb1, 0);
    k_hw2<<<gNR, HH>>>(gw2);
    k_spmm_gcn<<<gNR, HH>>>(gb2, 1);

    // 3) MRGCO layers (length-4 real-FFT == 4x4 cosine transform)
    int eltBlocks = (NN * HH + 255) / 256;
    for (int l = 0; l < LLAY; l++) {
        k_xhat<<<eltBlocks, 256>>>();
        k_spmm3<<<NN, HH>>>();
        k_ohat<<<eltBlocks, 256>>>();
        k_what<<<(HH * HH + 255) / 256, 256>>>(mw + (size_t)l * HH * HH * RR);
        k_dhat<<<dim3(NN / 8, 3), dim3(HH, 8)>>>();
        k_o2relu<<<eltBlocks, 256>>>();
    }

    // 4) head on the T gathered rows + deterministic loss reduction
    k_head<<<TT, HH>>>(target_x, target, l1w, l1b, l2w, l2b, y_dst);
    if (loss_ptr) k_loss_reduce<<<1, 256>>>(loss_ptr);
}